// round 1
// baseline (speedup 1.0000x reference)
#include <cuda_runtime.h>

// Problem constants
#define B_ 8
#define L_ 2048
#define H_ 1024

// Scratch: __device__ globals (no cudaMalloc allowed anywhere)
__device__ float g_q[(size_t)B_ * L_ * H_];   // 64 MB
__device__ float g_k[(size_t)B_ * L_ * H_];   // 64 MB
__device__ float g_v[(size_t)B_ * L_ * H_];   // 64 MB
__device__ float g_s[(size_t)B_ * L_ * L_];   // 128 MB

// ---------------- SGEMM tiling config ----------------
#define BM 128
#define BN 128
#define BKK 8
#define TM 8
#define TN 8
// 256 threads = 16x16, each computing an 8x8 micro-tile.

// C[M,N] = scale * (A[M,K] * B[N,K]^T + bias)   (both operands K-contiguous, "NT")
// Optional per-batch via blockIdx.z strides; optional diagonal mask (per-batch
// row==col -> -FLT_MAX) for attention scores.
__global__ __launch_bounds__(256) void gemm_nt(
    const float* __restrict__ A, const float* __restrict__ Bm,
    const float* __restrict__ bias, float* __restrict__ C,
    int M, int N, int K, float scale, int maskDiag,
    long long sA, long long sB, long long sC)
{
    A  += (long long)blockIdx.z * sA;
    Bm += (long long)blockIdx.z * sB;
    C  += (long long)blockIdx.z * sC;

    __shared__ float As[BKK][BM];
    __shared__ float Bs[BKK][BN];

    const int tid = threadIdx.x;
    const int tx = tid & 15;      // 0..15
    const int ty = tid >> 4;      // 0..15
    const int rowBase = blockIdx.y * BM;
    const int colBase = blockIdx.x * BN;

    // Global load mapping: 128 rows x 8 k-cols, one float4 per thread.
    const int lr = tid >> 1;            // 0..127
    const int lc = (tid & 1) * 4;       // 0 or 4
    const float* Aptr = A + (long long)(rowBase + lr) * K + lc;
    const float* Bptr = Bm + (long long)(colBase + lr) * K + lc;

    float acc[TM][TN];
#pragma unroll
    for (int i = 0; i < TM; i++)
#pragma unroll
        for (int j = 0; j < TN; j++) acc[i][j] = 0.0f;

    for (int k0 = 0; k0 < K; k0 += BKK) {
        float4 av = *reinterpret_cast<const float4*>(Aptr + k0);
        float4 bv = *reinterpret_cast<const float4*>(Bptr + k0);
        As[lc + 0][lr] = av.x; As[lc + 1][lr] = av.y;
        As[lc + 2][lr] = av.z; As[lc + 3][lr] = av.w;
        Bs[lc + 0][lr] = bv.x; Bs[lc + 1][lr] = bv.y;
        Bs[lc + 2][lr] = bv.z; Bs[lc + 3][lr] = bv.w;
        __syncthreads();

#pragma unroll
        for (int kk = 0; kk < BKK; kk++) {
            float a[TM], b[TN];
            *reinterpret_cast<float4*>(&a[0]) = *reinterpret_cast<const float4*>(&As[kk][ty * TM]);
            *reinterpret_cast<float4*>(&a[4]) = *reinterpret_cast<const float4*>(&As[kk][ty * TM + 4]);
            *reinterpret_cast<float4*>(&b[0]) = *reinterpret_cast<const float4*>(&Bs[kk][tx * TN]);
            *reinterpret_cast<float4*>(&b[4]) = *reinterpret_cast<const float4*>(&Bs[kk][tx * TN + 4]);
#pragma unroll
            for (int i = 0; i < TM; i++)
#pragma unroll
                for (int j = 0; j < TN; j++)
                    acc[i][j] = fmaf(a[i], b[j], acc[i][j]);
        }
        __syncthreads();
    }

#pragma unroll
    for (int i = 0; i < TM; i++) {
        const int r = rowBase + ty * TM + i;
#pragma unroll
        for (int j = 0; j < TN; j++) {
            const int c = colBase + tx * TN + j;
            float v = acc[i][j];
            if (bias) v += bias[c];
            v *= scale;
            if (maskDiag && (r == c)) v = -3.402823466e38f;  // -FLT_MAX
            C[(long long)r * N + c] = v;
        }
    }
}

// C[M,N] = A[M,K] * B[K,N]  ("NN": B is N-contiguous). Per-batch via blockIdx.z.
__global__ __launch_bounds__(256) void gemm_nn(
    const float* __restrict__ A, const float* __restrict__ Bm,
    float* __restrict__ C,
    int M, int N, int K,
    long long sA, long long sB, long long sC)
{
    A  += (long long)blockIdx.z * sA;
    Bm += (long long)blockIdx.z * sB;
    C  += (long long)blockIdx.z * sC;

    __shared__ float As[BKK][BM];
    __shared__ float Bs[BKK][BN];

    const int tid = threadIdx.x;
    const int tx = tid & 15;
    const int ty = tid >> 4;
    const int rowBase = blockIdx.y * BM;
    const int colBase = blockIdx.x * BN;

    // A tile: as in NT (K-contiguous)
    const int lr = tid >> 1;
    const int lc = (tid & 1) * 4;
    const float* Aptr = A + (long long)(rowBase + lr) * K + lc;

    // B tile: 8 k-rows x 128 n-cols, one float4 per thread, no transpose.
    const int br = tid >> 5;            // 0..7
    const int bc = (tid & 31) * 4;      // 0..124
    const float* Bptr = Bm + (long long)br * N + colBase + bc;

    float acc[TM][TN];
#pragma unroll
    for (int i = 0; i < TM; i++)
#pragma unroll
        for (int j = 0; j < TN; j++) acc[i][j] = 0.0f;

    for (int k0 = 0; k0 < K; k0 += BKK) {
        float4 av = *reinterpret_cast<const float4*>(Aptr + k0);
        float4 bv = *reinterpret_cast<const float4*>(Bptr + (long long)k0 * N);
        As[lc + 0][lr] = av.x; As[lc + 1][lr] = av.y;
        As[lc + 2][lr] = av.z; As[lc + 3][lr] = av.w;
        *reinterpret_cast<float4*>(&Bs[br][bc]) = bv;
        __syncthreads();

#pragma unroll
        for (int kk = 0; kk < BKK; kk++) {
            float a[TM], b[TN];
            *reinterpret_cast<float4*>(&a[0]) = *reinterpret_cast<const float4*>(&As[kk][ty * TM]);
            *reinterpret_cast<float4*>(&a[4]) = *reinterpret_cast<const float4*>(&As[kk][ty * TM + 4]);
            *reinterpret_cast<float4*>(&b[0]) = *reinterpret_cast<const float4*>(&Bs[kk][tx * TN]);
            *reinterpret_cast<float4*>(&b[4]) = *reinterpret_cast<const float4*>(&Bs[kk][tx * TN + 4]);
#pragma unroll
            for (int i = 0; i < TM; i++)
#pragma unroll
                for (int j = 0; j < TN; j++)
                    acc[i][j] = fmaf(a[i], b[j], acc[i][j]);
        }
        __syncthreads();
    }

#pragma unroll
    for (int i = 0; i < TM; i++) {
        const int r = rowBase + ty * TM + i;
#pragma unroll
        for (int j = 0; j < TN; j++) {
            const int c = colBase + tx * TN + j;
            C[(long long)r * N + c] = acc[i][j];
        }
    }
}

// In-place row softmax over 2048 columns. One block (256 threads) per row.
__global__ __launch_bounds__(256) void softmax_rows(float* __restrict__ S)
{
    __shared__ float red[256];
    float* row = S + (long long)blockIdx.x * L_;
    const int tid = threadIdx.x;

    float vals[8];
    float lmax = -3.402823466e38f;
#pragma unroll
    for (int i = 0; i < 8; i++) {
        vals[i] = row[tid + i * 256];
        lmax = fmaxf(lmax, vals[i]);
    }
    red[tid] = lmax;
    __syncthreads();
    for (int s = 128; s > 0; s >>= 1) {
        if (tid < s) red[tid] = fmaxf(red[tid], red[tid + s]);
        __syncthreads();
    }
    const float m = red[0];
    __syncthreads();

    float lsum = 0.0f;
#pragma unroll
    for (int i = 0; i < 8; i++) {
        vals[i] = __expf(vals[i] - m);   // -FLT_MAX diag -> exp underflows to 0
        lsum += vals[i];
    }
    red[tid] = lsum;
    __syncthreads();
    for (int s = 128; s > 0; s >>= 1) {
        if (tid < s) red[tid] += red[tid + s];
        __syncthreads();
    }
    const float inv = 1.0f / red[0];
#pragma unroll
    for (int i = 0; i < 8; i++) row[tid + i * 256] = vals[i] * inv;
}

extern "C" void kernel_launch(void* const* d_in, const int* in_sizes, int n_in,
                              void* d_out, int out_size)
{
    const float* x  = (const float*)d_in[0];
    const float* Wq = (const float*)d_in[1];
    const float* bq = (const float*)d_in[2];
    const float* Wk = (const float*)d_in[3];
    const float* bk = (const float*)d_in[4];
    const float* Wv = (const float*)d_in[5];
    const float* bv = (const float*)d_in[6];
    float* out = (float*)d_out;

    float *q, *k, *v, *s;
    cudaGetSymbolAddress((void**)&q, g_q);
    cudaGetSymbolAddress((void**)&k, g_k);
    cudaGetSymbolAddress((void**)&v, g_v);
    cudaGetSymbolAddress((void**)&s, g_s);

    const dim3 blk(256);
    const long long sQK = (long long)L_ * H_;
    const long long sSS = (long long)L_ * L_;

    // QKV projections: C[16384,1024] = x * W^T + b   (q folded with 1/H scale)
    dim3 gQKV(H_ / BN, (B_ * L_) / BM, 1);
    gemm_nt<<<gQKV, blk>>>(x, Wq, bq, q, B_ * L_, H_, H_, 1.0f / (float)H_, 0, 0, 0, 0);
    gemm_nt<<<gQKV, blk>>>(x, Wk, bk, k, B_ * L_, H_, H_, 1.0f, 0, 0, 0, 0);
    gemm_nt<<<gQKV, blk>>>(x, Wv, bv, v, B_ * L_, H_, H_, 1.0f, 0, 0, 0, 0);

    // Scores: S[b] = q[b] * k[b]^T, diagonal masked to -FLT_MAX
    dim3 gS(L_ / BN, L_ / BM, B_);
    gemm_nt<<<gS, blk>>>(q, k, nullptr, s, L_, L_, H_, 1.0f, 1, sQK, sQK, sSS);

    // Row softmax (in place)
    softmax_rows<<<B_ * L_, blk>>>(s);

    // Output: out[b] = S[b] * v[b]
    dim3 gO(H_ / BN, L_ / BM, B_);
    gemm_nn<<<gO, blk>>>(s, v, out, L_, H_, L_, sSS, sQK, sQK);
}

// round 2
// speedup vs baseline: 3.1513x; 3.1513x over previous
#include <cuda_runtime.h>

#define B_ 8
#define L_ 2048
#define H_ 1024

// Scratch: __device__ globals (no cudaMalloc allowed anywhere)
__device__ float g_q[(size_t)B_ * L_ * H_];   // 64 MB
__device__ float g_k[(size_t)B_ * L_ * H_];   // 64 MB
__device__ float g_v[(size_t)B_ * L_ * H_];   // 64 MB
__device__ float g_s[(size_t)B_ * L_ * L_];   // 128 MB

// ---------------- tf32 mma.sync GEMM config ----------------
// Block tile 128x128, BK=16. 8 warps as 2(M) x 4(N), warp tile 64x32.
// Each warp: 4 m-tiles (m16) x 4 n-tiles (n8), 2 k-steps (k8) per BK.
#define BMT 128
#define BNT 128
#define BKT 16
#define SA 20     // K-major smem row stride (floats): conflict-free frags
#define SB 136    // N-major smem row stride (floats): conflict-free frags

__device__ __forceinline__ unsigned f2tf(float f) {
    unsigned u;
    asm("cvt.rna.tf32.f32 %0, %1;" : "=r"(u) : "f"(f));
    return u;
}

__device__ __forceinline__ void mma_tf32(float& d0, float& d1, float& d2, float& d3,
                                         unsigned a0, unsigned a1, unsigned a2, unsigned a3,
                                         unsigned b0, unsigned b1) {
    asm volatile(
        "mma.sync.aligned.m16n8k8.row.col.f32.tf32.tf32.f32 "
        "{%0,%1,%2,%3}, {%4,%5,%6,%7}, {%8,%9}, {%0,%1,%2,%3};\n"
        : "+f"(d0), "+f"(d1), "+f"(d2), "+f"(d3)
        : "r"(a0), "r"(a1), "r"(a2), "r"(a3), "r"(b0), "r"(b1));
}

// C[M,N] = scale*(A[M,K] * B[N,K]^T + bias). Both operands K-contiguous.
// Optional batch via blockIdx.z strides; optional diagonal mask.
__global__ __launch_bounds__(256, 2) void gemm_nt_tc(
    const float* __restrict__ A, const float* __restrict__ Bm,
    const float* __restrict__ bias, float* __restrict__ C,
    int M, int N, int K, float scale, int maskDiag,
    long long sA, long long sB, long long sC)
{
    A  += (long long)blockIdx.z * sA;
    Bm += (long long)blockIdx.z * sB;
    C  += (long long)blockIdx.z * sC;

    __shared__ unsigned As[2][BMT * SA];
    __shared__ unsigned Bs[2][BNT * SA];

    const int tid  = threadIdx.x;
    const int warp = tid >> 5;
    const int lane = tid & 31;
    const int lq = lane >> 2;   // 0..7
    const int lr = lane & 3;    // 0..3
    const int wm = warp >> 2;   // 0..1
    const int wn = warp & 3;    // 0..3

    const int rowBase = blockIdx.y * BMT;
    const int colBase = blockIdx.x * BNT;

    // Global tile load mapping: 128 rows x 16 k, float4 along K; 2 per thread.
    const int gr = tid >> 2;            // 0..63 (and +64)
    const int gk = (tid & 3) * 4;       // 0,4,8,12
    const float* Ap0 = A  + (long long)(rowBase + gr) * K + gk;
    const float* Ap1 = A  + (long long)(rowBase + gr + 64) * K + gk;
    const float* Bp0 = Bm + (long long)(colBase + gr) * K + gk;
    const float* Bp1 = Bm + (long long)(colBase + gr + 64) * K + gk;

    float acc[4][4][4];
#pragma unroll
    for (int i = 0; i < 4; i++)
#pragma unroll
        for (int j = 0; j < 4; j++)
#pragma unroll
            for (int r = 0; r < 4; r++) acc[i][j][r] = 0.0f;

    const int sts0 = gr * SA + gk;
    const int sts1 = (gr + 64) * SA + gk;

    // Prologue: tile 0 -> buffer 0
    {
        float4 a0 = *(const float4*)Ap0, a1 = *(const float4*)Ap1;
        float4 b0 = *(const float4*)Bp0, b1 = *(const float4*)Bp1;
        *(uint4*)&As[0][sts0] = make_uint4(f2tf(a0.x), f2tf(a0.y), f2tf(a0.z), f2tf(a0.w));
        *(uint4*)&As[0][sts1] = make_uint4(f2tf(a1.x), f2tf(a1.y), f2tf(a1.z), f2tf(a1.w));
        *(uint4*)&Bs[0][sts0] = make_uint4(f2tf(b0.x), f2tf(b0.y), f2tf(b0.z), f2tf(b0.w));
        *(uint4*)&Bs[0][sts1] = make_uint4(f2tf(b1.x), f2tf(b1.y), f2tf(b1.z), f2tf(b1.w));
    }
    __syncthreads();

    const int ntiles = K / BKT;
    for (int kt = 0; kt < ntiles; kt++) {
        const int cur = kt & 1;
        float4 pa0, pa1, pb0, pb1;
        const bool pre = (kt + 1 < ntiles);
        if (pre) {
            const int off = (kt + 1) * BKT;
            pa0 = *(const float4*)(Ap0 + off);
            pa1 = *(const float4*)(Ap1 + off);
            pb0 = *(const float4*)(Bp0 + off);
            pb1 = *(const float4*)(Bp1 + off);
        }

#pragma unroll
        for (int ks = 0; ks < 2; ks++) {
            unsigned af[4][4], bf[4][2];
#pragma unroll
            for (int mt = 0; mt < 4; mt++) {
                const int base = (wm * 64 + mt * 16 + lq) * SA + ks * 8 + lr;
                af[mt][0] = As[cur][base];
                af[mt][1] = As[cur][base + 8 * SA];
                af[mt][2] = As[cur][base + 4];
                af[mt][3] = As[cur][base + 8 * SA + 4];
            }
#pragma unroll
            for (int nt = 0; nt < 4; nt++) {
                const int base = (wn * 32 + nt * 8 + lq) * SA + ks * 8 + lr;
                bf[nt][0] = Bs[cur][base];
                bf[nt][1] = Bs[cur][base + 4];
            }
#pragma unroll
            for (int mt = 0; mt < 4; mt++)
#pragma unroll
                for (int nt = 0; nt < 4; nt++)
                    mma_tf32(acc[mt][nt][0], acc[mt][nt][1], acc[mt][nt][2], acc[mt][nt][3],
                             af[mt][0], af[mt][1], af[mt][2], af[mt][3],
                             bf[nt][0], bf[nt][1]);
        }

        if (pre) {
            const int nxt = cur ^ 1;
            *(uint4*)&As[nxt][sts0] = make_uint4(f2tf(pa0.x), f2tf(pa0.y), f2tf(pa0.z), f2tf(pa0.w));
            *(uint4*)&As[nxt][sts1] = make_uint4(f2tf(pa1.x), f2tf(pa1.y), f2tf(pa1.z), f2tf(pa1.w));
            *(uint4*)&Bs[nxt][sts0] = make_uint4(f2tf(pb0.x), f2tf(pb0.y), f2tf(pb0.z), f2tf(pb0.w));
            *(uint4*)&Bs[nxt][sts1] = make_uint4(f2tf(pb1.x), f2tf(pb1.y), f2tf(pb1.z), f2tf(pb1.w));
            __syncthreads();
        }
    }

    // Epilogue
#pragma unroll
    for (int mt = 0; mt < 4; mt++) {
        const int row = rowBase + wm * 64 + mt * 16 + lq;
#pragma unroll
        for (int nt = 0; nt < 4; nt++) {
            const int col = colBase + wn * 32 + nt * 8 + 2 * lr;
            float v0 = acc[mt][nt][0], v1 = acc[mt][nt][1];
            float v2 = acc[mt][nt][2], v3 = acc[mt][nt][3];
            if (bias) { v0 += bias[col]; v1 += bias[col + 1]; v2 += bias[col]; v3 += bias[col + 1]; }
            v0 *= scale; v1 *= scale; v2 *= scale; v3 *= scale;
            if (maskDiag) {
                if (row == col)     v0 = -3.402823466e38f;
                if (row == col + 1) v1 = -3.402823466e38f;
                if (row + 8 == col)     v2 = -3.402823466e38f;
                if (row + 8 == col + 1) v3 = -3.402823466e38f;
            }
            *(float2*)&C[(long long)row * N + col]       = make_float2(v0, v1);
            *(float2*)&C[(long long)(row + 8) * N + col] = make_float2(v2, v3);
        }
    }
}

// C[M,N] = A[M,K] * B[K,N]  (B is N-contiguous). Batched via blockIdx.z.
__global__ __launch_bounds__(256, 2) void gemm_nn_tc(
    const float* __restrict__ A, const float* __restrict__ Bm,
    float* __restrict__ C, int M, int N, int K,
    long long sA, long long sB, long long sC)
{
    A  += (long long)blockIdx.z * sA;
    Bm += (long long)blockIdx.z * sB;
    C  += (long long)blockIdx.z * sC;

    __shared__ unsigned As[2][BMT * SA];
    __shared__ unsigned Bs[2][BKT * SB];

    const int tid  = threadIdx.x;
    const int warp = tid >> 5;
    const int lane = tid & 31;
    const int lq = lane >> 2;
    const int lr = lane & 3;
    const int wm = warp >> 2;
    const int wn = warp & 3;

    const int rowBase = blockIdx.y * BMT;
    const int colBase = blockIdx.x * BNT;

    // A: 128 rows x 16 k, float4 along K
    const int gr = tid >> 2;
    const int gk = (tid & 3) * 4;
    const float* Ap0 = A + (long long)(rowBase + gr) * K + gk;
    const float* Ap1 = A + (long long)(rowBase + gr + 64) * K + gk;
    const int stsA0 = gr * SA + gk;
    const int stsA1 = (gr + 64) * SA + gk;

    // B: 16 k-rows x 128 n, float4 along N
    const int bk = tid >> 5;            // 0..7 (and +8)
    const int bn = (tid & 31) * 4;      // 0..124
    const float* Bp0 = Bm + (long long)bk * N + colBase + bn;
    const float* Bp1 = Bm + (long long)(bk + 8) * N + colBase + bn;
    const int stsB0 = bk * SB + bn;
    const int stsB1 = (bk + 8) * SB + bn;

    float acc[4][4][4];
#pragma unroll
    for (int i = 0; i < 4; i++)
#pragma unroll
        for (int j = 0; j < 4; j++)
#pragma unroll
            for (int r = 0; r < 4; r++) acc[i][j][r] = 0.0f;

    {
        float4 a0 = *(const float4*)Ap0, a1 = *(const float4*)Ap1;
        float4 b0 = *(const float4*)Bp0, b1 = *(const float4*)Bp1;
        *(uint4*)&As[0][stsA0] = make_uint4(f2tf(a0.x), f2tf(a0.y), f2tf(a0.z), f2tf(a0.w));
        *(uint4*)&As[0][stsA1] = make_uint4(f2tf(a1.x), f2tf(a1.y), f2tf(a1.z), f2tf(a1.w));
        *(uint4*)&Bs[0][stsB0] = make_uint4(f2tf(b0.x), f2tf(b0.y), f2tf(b0.z), f2tf(b0.w));
        *(uint4*)&Bs[0][stsB1] = make_uint4(f2tf(b1.x), f2tf(b1.y), f2tf(b1.z), f2tf(b1.w));
    }
    __syncthreads();

    const int ntiles = K / BKT;
    for (int kt = 0; kt < ntiles; kt++) {
        const int cur = kt & 1;
        float4 pa0, pa1, pb0, pb1;
        const bool pre = (kt + 1 < ntiles);
        if (pre) {
            const int offA = (kt + 1) * BKT;
            const long long offB = (long long)(kt + 1) * BKT * N;
            pa0 = *(const float4*)(Ap0 + offA);
            pa1 = *(const float4*)(Ap1 + offA);
            pb0 = *(const float4*)(Bp0 + offB);
            pb1 = *(const float4*)(Bp1 + offB);
        }

#pragma unroll
        for (int ks = 0; ks < 2; ks++) {
            unsigned af[4][4], bf[4][2];
#pragma unroll
            for (int mt = 0; mt < 4; mt++) {
                const int base = (wm * 64 + mt * 16 + lq) * SA + ks * 8 + lr;
                af[mt][0] = As[cur][base];
                af[mt][1] = As[cur][base + 8 * SA];
                af[mt][2] = As[cur][base + 4];
                af[mt][3] = As[cur][base + 8 * SA + 4];
            }
#pragma unroll
            for (int nt = 0; nt < 4; nt++) {
                const int col = wn * 32 + nt * 8 + lq;
                bf[nt][0] = Bs[cur][(ks * 8 + lr) * SB + col];
                bf[nt][1] = Bs[cur][(ks * 8 + lr + 4) * SB + col];
            }
#pragma unroll
            for (int mt = 0; mt < 4; mt++)
#pragma unroll
                for (int nt = 0; nt < 4; nt++)
                    mma_tf32(acc[mt][nt][0], acc[mt][nt][1], acc[mt][nt][2], acc[mt][nt][3],
                             af[mt][0], af[mt][1], af[mt][2], af[mt][3],
                             bf[nt][0], bf[nt][1]);
        }

        if (pre) {
            const int nxt = cur ^ 1;
            *(uint4*)&As[nxt][stsA0] = make_uint4(f2tf(pa0.x), f2tf(pa0.y), f2tf(pa0.z), f2tf(pa0.w));
            *(uint4*)&As[nxt][stsA1] = make_uint4(f2tf(pa1.x), f2tf(pa1.y), f2tf(pa1.z), f2tf(pa1.w));
            *(uint4*)&Bs[nxt][stsB0] = make_uint4(f2tf(pb0.x), f2tf(pb0.y), f2tf(pb0.z), f2tf(pb0.w));
            *(uint4*)&Bs[nxt][stsB1] = make_uint4(f2tf(pb1.x), f2tf(pb1.y), f2tf(pb1.z), f2tf(pb1.w));
            __syncthreads();
        }
    }

#pragma unroll
    for (int mt = 0; mt < 4; mt++) {
        const int row = rowBase + wm * 64 + mt * 16 + lq;
#pragma unroll
        for (int nt = 0; nt < 4; nt++) {
            const int col = colBase + wn * 32 + nt * 8 + 2 * lr;
            *(float2*)&C[(long long)row * N + col] =
                make_float2(acc[mt][nt][0], acc[mt][nt][1]);
            *(float2*)&C[(long long)(row + 8) * N + col] =
                make_float2(acc[mt][nt][2], acc[mt][nt][3]);
        }
    }
}

// In-place row softmax over 2048 columns. One block (256 threads) per row.
__global__ __launch_bounds__(256) void softmax_rows(float* __restrict__ S)
{
    __shared__ float red[256];
    float* row = S + (long long)blockIdx.x * L_;
    const int tid = threadIdx.x;

    float vals[8];
    float lmax = -3.402823466e38f;
#pragma unroll
    for (int i = 0; i < 8; i++) {
        vals[i] = row[tid + i * 256];
        lmax = fmaxf(lmax, vals[i]);
    }
    red[tid] = lmax;
    __syncthreads();
    for (int s = 128; s > 0; s >>= 1) {
        if (tid < s) red[tid] = fmaxf(red[tid], red[tid + s]);
        __syncthreads();
    }
    const float m = red[0];
    __syncthreads();

    float lsum = 0.0f;
#pragma unroll
    for (int i = 0; i < 8; i++) {
        vals[i] = __expf(vals[i] - m);
        lsum += vals[i];
    }
    red[tid] = lsum;
    __syncthreads();
    for (int s = 128; s > 0; s >>= 1) {
        if (tid < s) red[tid] += red[tid + s];
        __syncthreads();
    }
    const float inv = 1.0f / red[0];
#pragma unroll
    for (int i = 0; i < 8; i++) row[tid + i * 256] = vals[i] * inv;
}

extern "C" void kernel_launch(void* const* d_in, const int* in_sizes, int n_in,
                              void* d_out, int out_size)
{
    const float* x  = (const float*)d_in[0];
    const float* Wq = (const float*)d_in[1];
    const float* bq = (const float*)d_in[2];
    const float* Wk = (const float*)d_in[3];
    const float* bk = (const float*)d_in[4];
    const float* Wv = (const float*)d_in[5];
    const float* bv = (const float*)d_in[6];
    float* out = (float*)d_out;

    float *q, *k, *v, *s;
    cudaGetSymbolAddress((void**)&q, g_q);
    cudaGetSymbolAddress((void**)&k, g_k);
    cudaGetSymbolAddress((void**)&v, g_v);
    cudaGetSymbolAddress((void**)&s, g_s);

    const dim3 blk(256);
    const long long sQK = (long long)L_ * H_;
    const long long sSS = (long long)L_ * L_;

    // QKV projections (q folded with 1/H scale)
    dim3 gQKV(H_ / BNT, (B_ * L_) / BMT, 1);
    gemm_nt_tc<<<gQKV, blk>>>(x, Wq, bq, q, B_ * L_, H_, H_, 1.0f / (float)H_, 0, 0, 0, 0);
    gemm_nt_tc<<<gQKV, blk>>>(x, Wk, bk, k, B_ * L_, H_, H_, 1.0f, 0, 0, 0, 0);
    gemm_nt_tc<<<gQKV, blk>>>(x, Wv, bv, v, B_ * L_, H_, H_, 1.0f, 0, 0, 0, 0);

    // Scores: S[b] = q[b] * k[b]^T, diagonal masked
    dim3 gS(L_ / BNT, L_ / BMT, B_);
    gemm_nt_tc<<<gS, blk>>>(q, k, nullptr, s, L_, L_, H_, 1.0f, 1, sQK, sQK, sSS);

    softmax_rows<<<B_ * L_, blk>>>(s);

    // Output: out[b] = S[b] * v[b]
    dim3 gO(H_ / BNT, L_ / BMT, B_);
    gemm_nn_tc<<<gO, blk>>>(s, v, out, L_, H_, L_, sSS, sQK, sQK);
}